// round 1
// baseline (speedup 1.0000x reference)
#include <cuda_runtime.h>

// Problem constants (fixed by the dataset)
#define IN_F   4096
#define OUT_F  4096
#define RANK   64
#define M_TOK  8192
#define SCALING 2.0f

// Scratch for W_eff = weight + SCALING * (P .* (Lambda*mask)) @ Q  -> [OUT_F, IN_F]
__device__ float g_weff[(size_t)OUT_F * IN_F];

// ---------------------------------------------------------------------------
// Kernel A: W_eff = weight + 2 * (P * lam) @ Q
// 64x64 output tile per block, 256 threads, 4x4 micro-tile per thread.
// ---------------------------------------------------------------------------
__global__ __launch_bounds__(256)
void weff_kernel(const float* __restrict__ weight,
                 const float* __restrict__ P,
                 const float* __restrict__ Lambda,
                 const float* __restrict__ Q,
                 const unsigned char* __restrict__ mask)
{
    __shared__ float lam[RANK];
    __shared__ float Ps[64][RANK + 1];   // [j][r], lambda pre-applied, padded
    __shared__ float Qs[RANK][64 + 1];   // [r][k], padded

    const int tid = threadIdx.x;
    const int j0 = blockIdx.y * 64;   // OUT_F dim
    const int k0 = blockIdx.x * 64;   // IN_F dim

    if (tid < RANK) {
        lam[tid] = SCALING * Lambda[tid] * (mask[tid] ? 1.0f : 0.0f);
    }
    __syncthreads();

    // Load P tile: rows j0..j0+63, all 64 ranks (contiguous per row)
    {
        const int r4 = (tid % 16) * 4;
        const int jj = tid / 16;     // 0..15
        #pragma unroll
        for (int p = 0; p < 4; p++) {
            const int j = jj + p * 16;
            float4 v = *reinterpret_cast<const float4*>(
                &P[(size_t)(j0 + j) * RANK + r4]);
            Ps[j][r4 + 0] = v.x * lam[r4 + 0];
            Ps[j][r4 + 1] = v.y * lam[r4 + 1];
            Ps[j][r4 + 2] = v.z * lam[r4 + 2];
            Ps[j][r4 + 3] = v.w * lam[r4 + 3];
        }
    }
    // Load Q tile: rows r=0..63, cols k0..k0+63
    {
        const int k4 = (tid % 16) * 4;
        const int rr = tid / 16;     // 0..15
        #pragma unroll
        for (int p = 0; p < 4; p++) {
            const int r = rr + p * 16;
            float4 v = *reinterpret_cast<const float4*>(
                &Q[(size_t)r * IN_F + k0 + k4]);
            Qs[r][k4 + 0] = v.x;
            Qs[r][k4 + 1] = v.y;
            Qs[r][k4 + 2] = v.z;
            Qs[r][k4 + 3] = v.w;
        }
    }
    __syncthreads();

    const int tx = tid % 16;   // k dim, 4 outputs
    const int ty = tid / 16;   // j dim, 4 outputs

    float acc[4][4] = {};
    #pragma unroll
    for (int r = 0; r < RANK; r++) {
        float a[4], b[4];
        #pragma unroll
        for (int i = 0; i < 4; i++) a[i] = Ps[ty * 4 + i][r];
        #pragma unroll
        for (int j = 0; j < 4; j++) b[j] = Qs[r][tx * 4 + j];
        #pragma unroll
        for (int i = 0; i < 4; i++)
            #pragma unroll
            for (int j = 0; j < 4; j++)
                acc[i][j] = fmaf(a[i], b[j], acc[i][j]);
    }

    // Epilogue: add weight, write W_eff
    #pragma unroll
    for (int i = 0; i < 4; i++) {
        const size_t row = (size_t)(j0 + ty * 4 + i);
        const size_t off = row * IN_F + k0 + tx * 4;
        float4 w = *reinterpret_cast<const float4*>(&weight[off]);
        w.x += acc[i][0];
        w.y += acc[i][1];
        w.z += acc[i][2];
        w.w += acc[i][3];
        *reinterpret_cast<float4*>(&g_weff[off]) = w;
    }
}

// ---------------------------------------------------------------------------
// Kernel B: out[M,N] = x[M,K] @ W_eff[N,K]^T   (NT SGEMM, both K-major)
// 128x128x16 tile, 256 threads, 8x8 per thread, float4 everywhere.
// ---------------------------------------------------------------------------
#define BM 128
#define BN 128
#define BK 16
#define TM 8
#define TN 8

__global__ __launch_bounds__(256, 2)
void sgemm_nt_kernel(const float* __restrict__ A,   // x     [M_TOK, IN_F]
                     float* __restrict__ C)         // out   [M_TOK, OUT_F]
{
    __shared__ float As[BK][BM];
    __shared__ float Bs[BK][BN];

    const float* __restrict__ B = g_weff;            // [OUT_F, IN_F]

    const int tid = threadIdx.x;
    const int m0 = blockIdx.y * BM;
    const int n0 = blockIdx.x * BN;

    // Global->shared loading geometry: 4 threads per row (16 floats = 4 float4)
    const int loadRow = tid / 4;           // 0..63
    const int loadK4  = (tid % 4) * 4;     // 0,4,8,12

    // Compute geometry
    const int tx = tid % 16;               // n dim
    const int ty = tid / 16;               // m dim

    float acc[TM][TN] = {};
    float ra[TM], rb[TN];

    const float* Aptr = A + (size_t)m0 * IN_F;
    const float* Bptr = B + (size_t)n0 * IN_F;

    for (int kt = 0; kt < IN_F; kt += BK) {
        // Load A tile (transposed into As[k][m])
        #pragma unroll
        for (int p = 0; p < 2; p++) {
            const int r = loadRow + p * 64;
            float4 v = *reinterpret_cast<const float4*>(
                &Aptr[(size_t)r * IN_F + kt + loadK4]);
            As[loadK4 + 0][r] = v.x;
            As[loadK4 + 1][r] = v.y;
            As[loadK4 + 2][r] = v.z;
            As[loadK4 + 3][r] = v.w;
        }
        // Load B tile (transposed into Bs[k][n])
        #pragma unroll
        for (int p = 0; p < 2; p++) {
            const int r = loadRow + p * 64;
            float4 v = *reinterpret_cast<const float4*>(
                &Bptr[(size_t)r * IN_F + kt + loadK4]);
            Bs[loadK4 + 0][r] = v.x;
            Bs[loadK4 + 1][r] = v.y;
            Bs[loadK4 + 2][r] = v.z;
            Bs[loadK4 + 3][r] = v.w;
        }
        __syncthreads();

        #pragma unroll
        for (int k = 0; k < BK; k++) {
            #pragma unroll
            for (int i = 0; i < TM; i += 4) {
                float4 v = *reinterpret_cast<const float4*>(&As[k][ty * TM + i]);
                ra[i + 0] = v.x; ra[i + 1] = v.y; ra[i + 2] = v.z; ra[i + 3] = v.w;
            }
            #pragma unroll
            for (int j = 0; j < TN; j += 4) {
                float4 v = *reinterpret_cast<const float4*>(&Bs[k][tx * TN + j]);
                rb[j + 0] = v.x; rb[j + 1] = v.y; rb[j + 2] = v.z; rb[j + 3] = v.w;
            }
            #pragma unroll
            for (int i = 0; i < TM; i++)
                #pragma unroll
                for (int j = 0; j < TN; j++)
                    acc[i][j] = fmaf(ra[i], rb[j], acc[i][j]);
        }
        __syncthreads();
    }

    // Store 8x8 per thread as float4s
    #pragma unroll
    for (int i = 0; i < TM; i++) {
        const size_t row = (size_t)(m0 + ty * TM + i);
        float* cp = C + row * OUT_F + n0 + tx * TN;
        #pragma unroll
        for (int j = 0; j < TN; j += 4) {
            float4 v = make_float4(acc[i][j], acc[i][j + 1],
                                   acc[i][j + 2], acc[i][j + 3]);
            *reinterpret_cast<float4*>(cp + j) = v;
        }
    }
}

// ---------------------------------------------------------------------------
// Launch
// Inputs (metadata order): 0=x, 1=weight, 2=P, 3=Lambda, 4=Q, 5=rank_mask
// ---------------------------------------------------------------------------
extern "C" void kernel_launch(void* const* d_in, const int* in_sizes, int n_in,
                              void* d_out, int out_size)
{
    const float* x      = (const float*)d_in[0];
    const float* weight = (const float*)d_in[1];
    const float* P      = (const float*)d_in[2];
    const float* Lambda = (const float*)d_in[3];
    const float* Q      = (const float*)d_in[4];
    const unsigned char* mask = (const unsigned char*)d_in[5];
    float* out = (float*)d_out;

    // Kernel A: build W_eff
    {
        dim3 grid(IN_F / 64, OUT_F / 64);
        weff_kernel<<<grid, 256>>>(weight, P, Lambda, Q, mask);
    }
    // Kernel B: out = x @ W_eff^T
    {
        dim3 grid(OUT_F / BN, M_TOK / BM);
        sgemm_nt_kernel<<<grid, 256>>>(x, out);
    }
}

// round 3
// speedup vs baseline: 2.8232x; 2.8232x over previous
#include <cuda_runtime.h>
#include <cuda_bf16.h>
#include <cstdint>

// Problem constants (fixed by the dataset)
#define IN_F   4096
#define OUT_F  4096
#define RANK   64
#define M_TOK  8192
#define SCALING 2.0f

// ---------------------------------------------------------------------------
// Device scratch: bf16 hi/lo splits of x and W_eff
// ---------------------------------------------------------------------------
__device__ __nv_bfloat16 g_xhi[(size_t)M_TOK * IN_F];
__device__ __nv_bfloat16 g_xlo[(size_t)M_TOK * IN_F];
__device__ __nv_bfloat16 g_whi[(size_t)OUT_F * IN_F];
__device__ __nv_bfloat16 g_wlo[(size_t)OUT_F * IN_F];

// ---------------------------------------------------------------------------
// Helpers
// ---------------------------------------------------------------------------
__device__ __forceinline__ uint32_t smem_to_u32(const void* p) {
    uint32_t a;
    asm("{ .reg .u64 t; cvta.to.shared.u64 t, %1; cvt.u32.u64 %0, t; }"
        : "=r"(a) : "l"(p));
    return a;
}

__device__ __forceinline__ void cp16(uint32_t sdst, const void* gsrc) {
    asm volatile("cp.async.cg.shared.global [%0], [%1], 16;"
                 :: "r"(sdst), "l"(gsrc));
}

__device__ __forceinline__ void ldsm4(uint32_t* r, uint32_t addr) {
    asm volatile("ldmatrix.sync.aligned.m8n8.x4.shared.b16 {%0,%1,%2,%3}, [%4];"
                 : "=r"(r[0]), "=r"(r[1]), "=r"(r[2]), "=r"(r[3])
                 : "r"(addr));
}

__device__ __forceinline__ void mma16816(float* c, const uint32_t* a,
                                         uint32_t b0, uint32_t b1) {
    asm volatile(
        "mma.sync.aligned.m16n8k16.row.col.f32.bf16.bf16.f32 "
        "{%0,%1,%2,%3}, {%4,%5,%6,%7}, {%8,%9}, {%0,%1,%2,%3};"
        : "+f"(c[0]), "+f"(c[1]), "+f"(c[2]), "+f"(c[3])
        : "r"(a[0]), "r"(a[1]), "r"(a[2]), "r"(a[3]), "r"(b0), "r"(b1));
}

// SW64 swizzle for 64-byte rows (16B granules)
__device__ __forceinline__ uint32_t sw64(uint32_t off) {
    return off ^ ((off >> 3) & 0x30);
}

// ---------------------------------------------------------------------------
// Kernel A: W_eff = weight + 2*(P .* lam) @ Q, split into bf16 hi/lo
// ---------------------------------------------------------------------------
__global__ __launch_bounds__(256)
void weff_kernel(const float* __restrict__ weight,
                 const float* __restrict__ P,
                 const float* __restrict__ Lambda,
                 const float* __restrict__ Q,
                 const unsigned char* __restrict__ mask)
{
    __shared__ float lam[RANK];
    __shared__ float Ps[64][RANK + 1];
    __shared__ float Qs[RANK][64 + 1];

    const int tid = threadIdx.x;
    const int j0 = blockIdx.y * 64;
    const int k0 = blockIdx.x * 64;

    if (tid < RANK)
        lam[tid] = SCALING * Lambda[tid] * (mask[tid] ? 1.0f : 0.0f);
    __syncthreads();

    {
        const int r4 = (tid % 16) * 4;
        const int jj = tid / 16;
        #pragma unroll
        for (int p = 0; p < 4; p++) {
            const int j = jj + p * 16;
            float4 v = *reinterpret_cast<const float4*>(&P[(size_t)(j0 + j) * RANK + r4]);
            Ps[j][r4 + 0] = v.x * lam[r4 + 0];
            Ps[j][r4 + 1] = v.y * lam[r4 + 1];
            Ps[j][r4 + 2] = v.z * lam[r4 + 2];
            Ps[j][r4 + 3] = v.w * lam[r4 + 3];
        }
        const int k4 = (tid % 16) * 4;
        const int rr = tid / 16;
        #pragma unroll
        for (int p = 0; p < 4; p++) {
            const int r = rr + p * 16;
            float4 v = *reinterpret_cast<const float4*>(&Q[(size_t)r * IN_F + k0 + k4]);
            Qs[r][k4 + 0] = v.x;
            Qs[r][k4 + 1] = v.y;
            Qs[r][k4 + 2] = v.z;
            Qs[r][k4 + 3] = v.w;
        }
    }
    __syncthreads();

    const int tx = tid % 16;
    const int ty = tid / 16;

    float acc[4][4] = {};
    #pragma unroll
    for (int r = 0; r < RANK; r++) {
        float a[4], b[4];
        #pragma unroll
        for (int i = 0; i < 4; i++) a[i] = Ps[ty * 4 + i][r];
        #pragma unroll
        for (int j = 0; j < 4; j++) b[j] = Qs[r][tx * 4 + j];
        #pragma unroll
        for (int i = 0; i < 4; i++)
            #pragma unroll
            for (int j = 0; j < 4; j++)
                acc[i][j] = fmaf(a[i], b[j], acc[i][j]);
    }

    #pragma unroll
    for (int i = 0; i < 4; i++) {
        const size_t row = (size_t)(j0 + ty * 4 + i);
        const size_t off = row * IN_F + k0 + tx * 4;
        float4 wv = *reinterpret_cast<const float4*>(&weight[off]);
        float w[4] = { wv.x + acc[i][0], wv.y + acc[i][1],
                       wv.z + acc[i][2], wv.w + acc[i][3] };
        __nv_bfloat16 h[4], l[4];
        #pragma unroll
        for (int j = 0; j < 4; j++) {
            h[j] = __float2bfloat16_rn(w[j]);
            l[j] = __float2bfloat16_rn(w[j] - __bfloat162float(h[j]));
        }
        *reinterpret_cast<__nv_bfloat162*>(&g_whi[off])     = __halves2bfloat162(h[0], h[1]);
        *reinterpret_cast<__nv_bfloat162*>(&g_whi[off + 2]) = __halves2bfloat162(h[2], h[3]);
        *reinterpret_cast<__nv_bfloat162*>(&g_wlo[off])     = __halves2bfloat162(l[0], l[1]);
        *reinterpret_cast<__nv_bfloat162*>(&g_wlo[off + 2]) = __halves2bfloat162(l[2], l[3]);
    }
}

// ---------------------------------------------------------------------------
// Kernel B: split x into bf16 hi/lo
// ---------------------------------------------------------------------------
__global__ __launch_bounds__(256)
void split_x_kernel(const float* __restrict__ x)
{
    const size_t i = ((size_t)blockIdx.x * 256 + threadIdx.x) * 4;
    float4 v = *reinterpret_cast<const float4*>(x + i);
    float w[4] = { v.x, v.y, v.z, v.w };
    __nv_bfloat16 h[4], l[4];
    #pragma unroll
    for (int j = 0; j < 4; j++) {
        h[j] = __float2bfloat16_rn(w[j]);
        l[j] = __float2bfloat16_rn(w[j] - __bfloat162float(h[j]));
    }
    *reinterpret_cast<__nv_bfloat162*>(&g_xhi[i])     = __halves2bfloat162(h[0], h[1]);
    *reinterpret_cast<__nv_bfloat162*>(&g_xhi[i + 2]) = __halves2bfloat162(h[2], h[3]);
    *reinterpret_cast<__nv_bfloat162*>(&g_xlo[i])     = __halves2bfloat162(l[0], l[1]);
    *reinterpret_cast<__nv_bfloat162*>(&g_xlo[i + 2]) = __halves2bfloat162(l[2], l[3]);
}

// ---------------------------------------------------------------------------
// Kernel C: split-bf16 GEMM on mma.sync (HMMA)
//   out[M,N] = Xhi@Whi^T + Xhi@Wlo^T + Xlo@Whi^T  (fp32 accum in registers)
// 128x128 tile, KC=32, 4-stage cp.async ring, 256 threads (8 warps, 2x4).
// ---------------------------------------------------------------------------
#define BM 128
#define BN 128
#define KC 32
#define STAGES 4
#define NK (IN_F / KC)                  // 128 k-tiles
#define TILE_B (128 * 64)               // 8 KB: 128 rows x 64B (KC bf16)
#define STAGE_B (4 * TILE_B)            // 32 KB: Ahi, Alo, Bhi, Blo
#define GEMM_SMEM (STAGES * STAGE_B)    // 128 KB

// Load one 128-row x 64B tile (k-chunk kt) into swizzled SMEM via cp.async
__device__ __forceinline__ void load_tile(uint32_t sdst,
                                          const __nv_bfloat16* g,
                                          int kt, int tid)
{
    const char* gb = (const char*)g + (size_t)kt * (KC * 2);   // 64B per chunk
    #pragma unroll
    for (int i = 0; i < 2; i++) {
        const int slot = tid + i * 256;          // 0..511
        const int row = slot >> 2;               // 0..127
        const int c16 = slot & 3;                // 0..3
        const uint32_t off = (uint32_t)(row * 64 + c16 * 16);
        cp16(sdst + sw64(off), gb + (size_t)row * (IN_F * 2) + c16 * 16);
    }
}

__device__ __forceinline__ void load_chunk(uint32_t stage_base,
                                           const __nv_bfloat16* gAhi,
                                           const __nv_bfloat16* gAlo,
                                           const __nv_bfloat16* gBhi,
                                           const __nv_bfloat16* gBlo,
                                           int kt, int tid)
{
    load_tile(stage_base + 0 * TILE_B, gAhi, kt, tid);
    load_tile(stage_base + 1 * TILE_B, gAlo, kt, tid);
    load_tile(stage_base + 2 * TILE_B, gBhi, kt, tid);
    load_tile(stage_base + 3 * TILE_B, gBlo, kt, tid);
}

__global__ __launch_bounds__(256, 1)
void gemm_kernel(float* __restrict__ out)
{
    extern __shared__ char smem[];
    const uint32_t sbase = smem_to_u32(smem);
    const int tid = threadIdx.x;
    const int wid = tid >> 5;
    const int lane = tid & 31;

    const int n0 = blockIdx.x * BN;
    const int m0 = blockIdx.y * BM;

    const int wm = wid >> 2;           // 0..1  -> 64 rows of M
    const int wn = wid & 3;            // 0..3  -> 32 cols of N

    const __nv_bfloat16* gAhi = g_xhi + (size_t)m0 * IN_F;
    const __nv_bfloat16* gAlo = g_xlo + (size_t)m0 * IN_F;
    const __nv_bfloat16* gBhi = g_whi + (size_t)n0 * IN_F;
    const __nv_bfloat16* gBlo = g_wlo + (size_t)n0 * IN_F;

    // Prologue: fill STAGES-1 stages
    #pragma unroll
    for (int c = 0; c < STAGES - 1; c++) {
        load_chunk(sbase + c * STAGE_B, gAhi, gAlo, gBhi, gBlo, c, tid);
        asm volatile("cp.async.commit_group;" ::: "memory");
    }

    float acc[4][4][4] = {};   // [mt][nt][frag]

    // Per-lane intra-fragment offsets (byte offsets within a tile, pre-swizzle)
    // A: row = warp_m_base + (lane&15) (+mt*16), kbyte = (lane>=16)*16 (+kstep*32)
    const uint32_t a_row = (uint32_t)(wm * 64 + (lane & 15));
    const uint32_t a_kb  = (uint32_t)((lane >> 4) << 4);
    // B: row = warp_n_base + ((lane&16)>>1) + (lane&7) (+ntp*16), kbyte = ((lane&8)<<1) (+kstep*32)
    const uint32_t b_row = (uint32_t)(wn * 32 + ((lane & 16) >> 1) + (lane & 7));
    const uint32_t b_kb  = (uint32_t)((lane & 8) << 1);

    for (int kt = 0; kt < NK; kt++) {
        asm volatile("cp.async.wait_group %0;" :: "n"(STAGES - 2) : "memory");
        __syncthreads();

        // Prefetch stage kt+STAGES-1 (overwrites stage consumed at kt-1)
        if (kt + STAGES - 1 < NK) {
            load_chunk(sbase + ((kt + STAGES - 1) % STAGES) * STAGE_B,
                       gAhi, gAlo, gBhi, gBlo, kt + STAGES - 1, tid);
        }
        asm volatile("cp.async.commit_group;" ::: "memory");

        const uint32_t sb = sbase + (kt % STAGES) * STAGE_B;

        #pragma unroll
        for (int ks = 0; ks < 2; ks++) {
            uint32_t ahi[4][4], alo[4][4];
            uint32_t bhi[2][4], blo[2][4];

            #pragma unroll
            for (int mt = 0; mt < 4; mt++) {
                const uint32_t off = sw64((a_row + mt * 16) * 64 + a_kb + ks * 32);
                ldsm4(ahi[mt], sb + 0 * TILE_B + off);
                ldsm4(alo[mt], sb + 1 * TILE_B + off);
            }
            #pragma unroll
            for (int np = 0; np < 2; np++) {
                const uint32_t off = sw64((b_row + np * 16) * 64 + b_kb + ks * 32);
                ldsm4(bhi[np], sb + 2 * TILE_B + off);
                ldsm4(blo[np], sb + 3 * TILE_B + off);
            }

            #pragma unroll
            for (int mt = 0; mt < 4; mt++) {
                #pragma unroll
                for (int nt = 0; nt < 4; nt++) {
                    const int np = nt >> 1;
                    const int hb = (nt & 1) * 2;
                    // hh
                    mma16816(acc[mt][nt], ahi[mt], bhi[np][hb], bhi[np][hb + 1]);
                    // hl
                    mma16816(acc[mt][nt], ahi[mt], blo[np][hb], blo[np][hb + 1]);
                    // lh
                    mma16816(acc[mt][nt], alo[mt], bhi[np][hb], bhi[np][hb + 1]);
                }
            }
        }
        __syncthreads();
    }

    // Epilogue: direct fp32 stores (d-frag: rows lane/4 & lane/4+8, cols (lane%4)*2)
    const int r_lo = lane >> 2;
    const int c_lo = (lane & 3) * 2;
    #pragma unroll
    for (int mt = 0; mt < 4; mt++) {
        const size_t row0 = (size_t)(m0 + wm * 64 + mt * 16 + r_lo);
        #pragma unroll
        for (int nt = 0; nt < 4; nt++) {
            const size_t col = (size_t)(n0 + wn * 32 + nt * 8 + c_lo);
            float2 v0 = make_float2(acc[mt][nt][0], acc[mt][nt][1]);
            float2 v1 = make_float2(acc[mt][nt][2], acc[mt][nt][3]);
            *reinterpret_cast<float2*>(out + row0 * OUT_F + col) = v0;
            *reinterpret_cast<float2*>(out + (row0 + 8) * OUT_F + col) = v1;
        }
    }
}

// ---------------------------------------------------------------------------
// Launch.  Inputs: 0=x, 1=weight, 2=P, 3=Lambda, 4=Q, 5=rank_mask
// ---------------------------------------------------------------------------
extern "C" void kernel_launch(void* const* d_in, const int* in_sizes, int n_in,
                              void* d_out, int out_size)
{
    const float* x      = (const float*)d_in[0];
    const float* weight = (const float*)d_in[1];
    const float* P      = (const float*)d_in[2];
    const float* Lambda = (const float*)d_in[3];
    const float* Q      = (const float*)d_in[4];
    const unsigned char* mask = (const unsigned char*)d_in[5];
    float* out = (float*)d_out;

    cudaFuncSetAttribute(gemm_kernel,
                         cudaFuncAttributeMaxDynamicSharedMemorySize, GEMM_SMEM);

    // A: W_eff hi/lo
    {
        dim3 grid(IN_F / 64, OUT_F / 64);
        weff_kernel<<<grid, 256>>>(weight, P, Lambda, Q, mask);
    }
    // B: x hi/lo
    {
        const int nblk = (int)(((size_t)M_TOK * IN_F) / (4 * 256));
        split_x_kernel<<<nblk, 256>>>(x);
    }
    // C: tensor-core GEMM (mma.sync)
    {
        dim3 grid(OUT_F / BN, M_TOK / BM);
        gemm_kernel<<<grid, 256, GEMM_SMEM>>>(out);
    }
}